// round 1
// baseline (speedup 1.0000x reference)
#include <cuda_runtime.h>
#include <cstddef>

#define BB 8
#define NN 2048
#define NODES (BB*NN)          // 16384
#define FP 72                  // padded feature width (66 real)
#define DSZ 32
#define TM 128
#define TK 16

// ---------------- scratch (device globals, no allocation) ----------------
__device__ float g_X[NODES*FP];
__device__ float g_C[NODES*FP];
__device__ float g_state[NODES*DSZ];
__device__ float g_r[NODES*DSZ];
__device__ float g_T1[2*NODES*FP];
__device__ float g_T2[2*NODES*FP];
__device__ float g_U1[2*NODES*FP];
__device__ float g_U2[2*NODES*FP];

// ---------------- f32x2 helpers (Blackwell packed fp32) ----------------
__device__ __forceinline__ unsigned long long pk2(float lo, float hi){
    unsigned long long r;
    asm("mov.b64 %0, {%1,%2};" : "=l"(r) : "f"(lo), "f"(hi));
    return r;
}
__device__ __forceinline__ void fma2(unsigned long long &d, unsigned long long a, unsigned long long b){
    asm("fma.rn.f32x2 %0, %1, %2, %0;" : "+l"(d) : "l"(a), "l"(b));
}
__device__ __forceinline__ float2 upk2(unsigned long long v){
    float lo, hi;
    asm("mov.b64 {%0,%1}, %2;" : "=f"(lo), "=f"(hi) : "l"(v));
    return make_float2(lo, hi);
}
__device__ __forceinline__ float sigmoidf_(float x){ return 1.f/(1.f+__expf(-x)); }

// ---------------- setup: mr/state + padded X ----------------
__global__ void setup_kernel(const float* __restrict__ xt, const float* __restrict__ s1,
                             const float* __restrict__ s2, const float* __restrict__ ge,
                             const float* __restrict__ mlp_w, const float* __restrict__ mlp_b)
{
    __shared__ float w[74*32];
    __shared__ float wb[32];
    const int tid = threadIdx.x;
    for (int i = tid; i < 74*32; i += blockDim.x) w[i] = mlp_w[i];
    if (tid < 32) wb[tid] = mlp_b[tid];
    __syncthreads();

    const int node = blockIdx.x*blockDim.x + tid;

    float in[74];
    #pragma unroll
    for (int i=0;i<2;i++)  in[i]    = xt[node*2+i];
    #pragma unroll
    for (int i=0;i<32;i++) in[2+i]  = s1[node*32+i];
    #pragma unroll
    for (int i=0;i<32;i++) in[34+i] = s2[node*32+i];
    #pragma unroll
    for (int i=0;i<8;i++)  in[66+i] = ge[node*8+i];

    float acc[32];
    #pragma unroll
    for (int o=0;o<32;o++) acc[o] = wb[o];
    for (int i=0;i<74;i++){
        float v = in[i];
        #pragma unroll
        for (int o=0;o<32;o++) acc[o] += v * w[i*32+o];
    }
    #pragma unroll
    for (int o=0;o<32;o++){
        float mr = sigmoidf_(acc[o]);
        g_state[node*32+o] = mr*in[2+o] + (1.f-mr)*in[34+o];
    }

    float* X = g_X + (size_t)node*FP;
    X[0]=in[0]; X[1]=in[1];
    #pragma unroll
    for (int i=0;i<32;i++){ X[2+i]=in[2+i]; X[34+i]=in[34+i]; }
    #pragma unroll
    for (int i=66;i<FP;i++) X[i]=0.f;
}

// ---------------- big GEMM: Out = A @ In  (or 2*A@In - Sub) ----------------
// grid: (NN/TM, B, 2 supports), block: 288 threads (tx=row-group 0..31, ty=col-group 0..8)
__global__ __launch_bounds__(288, 2)
void big_gemm(const float* __restrict__ Abase, const float* __restrict__ Inbase,
              float* __restrict__ Outbase, const float* __restrict__ Subbase,
              int inPerSupport, int combo)
{
    __shared__ __align__(16) float As[2][TK][132];   // transposed: As[k][row], padded stride
    __shared__ __align__(16) float Xs[2][TK][FP];

    const int b = blockIdx.y, s = blockIdx.z;
    const int sb = s*BB + b;
    const float* A  = Abase + (size_t)sb*NN*NN;
    const float* In = Inbase + (size_t)(inPerSupport ? sb : b)*NN*FP;
    float* Out = Outbase + (size_t)sb*NN*FP;

    const int tid = threadIdx.x;
    const int tx = tid & 31;        // 4 rows each -> 128 rows
    const int ty = tid >> 5;        // 8 cols each -> 72 cols
    const int rowBase = blockIdx.x*TM;

    unsigned long long acc[4][4];
    #pragma unroll
    for (int i=0;i<4;i++)
        #pragma unroll
        for (int j=0;j<4;j++) acc[i][j] = 0ull;

    // load mapping
    const int f0 = tid, f1 = tid + 288;
    const bool h2 = (f1 < 512);
    const int r0 = f0 >> 2, kq0 = f0 & 3;
    const int r1 = f1 >> 2, kq1 = f1 & 3;
    const int xk = tid / 18, xc = (tid % 18)*4;

    float4 ra0, ra1, rx;
    // prologue: fetch tile k0=0, store to buffer 0
    ra0 = *(const float4*)(A + (size_t)(rowBase + r0)*NN + kq0*4);
    if (h2) ra1 = *(const float4*)(A + (size_t)(rowBase + r1)*NN + kq1*4);
    rx = *(const float4*)(In + (size_t)xk*FP + xc);
    As[0][kq0*4+0][r0]=ra0.x; As[0][kq0*4+1][r0]=ra0.y; As[0][kq0*4+2][r0]=ra0.z; As[0][kq0*4+3][r0]=ra0.w;
    if (h2){ As[0][kq1*4+0][r1]=ra1.x; As[0][kq1*4+1][r1]=ra1.y; As[0][kq1*4+2][r1]=ra1.z; As[0][kq1*4+3][r1]=ra1.w; }
    *(float4*)&Xs[0][xk][xc] = rx;
    __syncthreads();

    int cur = 0;
    for (int k0 = 0; k0 < NN; k0 += TK){
        const int kn = k0 + TK;
        if (kn < NN){
            ra0 = *(const float4*)(A + (size_t)(rowBase + r0)*NN + kn + kq0*4);
            if (h2) ra1 = *(const float4*)(A + (size_t)(rowBase + r1)*NN + kn + kq1*4);
            rx = *(const float4*)(In + (size_t)(kn + xk)*FP + xc);
        }
        #pragma unroll
        for (int k=0;k<TK;k++){
            const float4 a = *(const float4*)&As[cur][k][tx*4];
            const unsigned long long xp0 = *(const unsigned long long*)&Xs[cur][k][ty*8 + 0];
            const unsigned long long xp1 = *(const unsigned long long*)&Xs[cur][k][ty*8 + 2];
            const unsigned long long xp2 = *(const unsigned long long*)&Xs[cur][k][ty*8 + 4];
            const unsigned long long xp3 = *(const unsigned long long*)&Xs[cur][k][ty*8 + 6];
            float av[4] = {a.x, a.y, a.z, a.w};
            #pragma unroll
            for (int i=0;i<4;i++){
                const unsigned long long ad = pk2(av[i], av[i]);
                fma2(acc[i][0], ad, xp0);
                fma2(acc[i][1], ad, xp1);
                fma2(acc[i][2], ad, xp2);
                fma2(acc[i][3], ad, xp3);
            }
        }
        if (kn < NN){
            const int nxt = cur ^ 1;
            As[nxt][kq0*4+0][r0]=ra0.x; As[nxt][kq0*4+1][r0]=ra0.y; As[nxt][kq0*4+2][r0]=ra0.z; As[nxt][kq0*4+3][r0]=ra0.w;
            if (h2){ As[nxt][kq1*4+0][r1]=ra1.x; As[nxt][kq1*4+1][r1]=ra1.y; As[nxt][kq1*4+2][r1]=ra1.z; As[nxt][kq1*4+3][r1]=ra1.w; }
            *(float4*)&Xs[nxt][xk][xc] = rx;
        }
        __syncthreads();
        cur ^= 1;
    }

    const float* Sub = combo ? (Subbase + (size_t)b*NN*FP) : nullptr;
    #pragma unroll
    for (int i=0;i<4;i++){
        const int row = rowBase + tx*4 + i;
        float v[8];
        #pragma unroll
        for (int j=0;j<4;j++){ float2 p = upk2(acc[i][j]); v[2*j]=p.x; v[2*j+1]=p.y; }
        if (combo){
            #pragma unroll
            for (int c=0;c<8;c++) v[c] = 2.f*v[c] - Sub[(size_t)row*FP + ty*8 + c];
        }
        *(float4*)(Out + (size_t)row*FP + ty*8)     = make_float4(v[0],v[1],v[2],v[3]);
        *(float4*)(Out + (size_t)row*FP + ty*8 + 4) = make_float4(v[4],v[5],v[6],v[7]);
    }
}

// ---------------- gate: zz = sigmoid(xg @ gate_w + b); build C, r ----------------
// block: 256 threads, 64 nodes per block. tx:2 nodes each, ty:12 cols each (96 cols)
__global__ __launch_bounds__(256)
void gate_kernel(const float* __restrict__ gate_w, const float* __restrict__ gate_b,
                 const float* __restrict__ xt, const float* __restrict__ s1, const float* __restrict__ s2)
{
    __shared__ __align__(16) float Ws[66*96];   // reused as zbuf[64*96] after
    __shared__ float xs[64][67];
    const int tid = threadIdx.x;
    const int tx = tid & 31, ty = tid >> 5;
    const int nodeBase = blockIdx.x*64;

    unsigned long long acc[2][6];
    #pragma unroll
    for (int i=0;i<2;i++)
        #pragma unroll
        for (int j=0;j<6;j++) acc[i][j]=0ull;

    const float* srcs[6] = { g_X, g_T1, g_T2, g_X, g_T1 + (size_t)NODES*FP, g_T2 + (size_t)NODES*FP };

    for (int t=0;t<6;t++){
        __syncthreads();
        for (int i = tid*4; i < 66*96; i += 1024)
            *(float4*)&Ws[i] = *(const float4*)&gate_w[t*66*96 + i];
        for (int i = tid; i < 64*66; i += 256){
            int n = i/66, k = i - n*66;
            xs[n][k] = srcs[t][(size_t)(nodeBase+n)*FP + k];
        }
        __syncthreads();
        for (int k=0;k<66;k++){
            const float x0 = xs[tx*2][k], x1 = xs[tx*2+1][k];
            const unsigned long long xd0 = pk2(x0,x0), xd1 = pk2(x1,x1);
            #pragma unroll
            for (int j=0;j<6;j++){
                const unsigned long long w = *(const unsigned long long*)&Ws[k*96 + ty*12 + 2*j];
                fma2(acc[0][j], xd0, w);
                fma2(acc[1][j], xd1, w);
            }
        }
    }
    __syncthreads();
    float* zbuf = Ws;   // 64*96 <= 66*96
    #pragma unroll
    for (int i=0;i<2;i++){
        #pragma unroll
        for (int j=0;j<6;j++){
            float2 p = upk2(acc[i][j]);
            const int col = ty*12 + 2*j;
            zbuf[(tx*2+i)*96 + col]   = sigmoidf_(p.x + gate_b[col]);
            zbuf[(tx*2+i)*96 + col+1] = sigmoidf_(p.y + gate_b[col+1]);
        }
    }
    __syncthreads();
    for (int i = tid; i < 64*32; i += 256){
        const int n = i >> 5, o = i & 31;
        const int node = nodeBase + n;
        const float z1 = zbuf[n*96+o], z2 = zbuf[n*96+32+o], rr = zbuf[n*96+64+o];
        g_C[(size_t)node*FP + 2 + o]  = z1 * s1[node*32+o];
        g_C[(size_t)node*FP + 34 + o] = z2 * s2[node*32+o];
        g_r[node*32+o] = rr;
    }
    if (tid < 64){
        const int node = nodeBase + tid;
        g_C[(size_t)node*FP + 0] = xt[node*2+0];
        g_C[(size_t)node*FP + 1] = xt[node*2+1];
        #pragma unroll
        for (int p=66;p<FP;p++) g_C[(size_t)node*FP + p] = 0.f;
    }
}

// ---------------- final: hc = tanh(xg' @ upd_w + b); h; trans ----------------
__global__ __launch_bounds__(256)
void final_kernel(const float* __restrict__ upd_w, const float* __restrict__ upd_b,
                  const float* __restrict__ hop_w, const float* __restrict__ hop_b,
                  float* __restrict__ out)
{
    __shared__ __align__(16) float Ws[66*32];
    __shared__ float xs[64][67];
    __shared__ float hbuf[64][33];
    __shared__ float hw[32*32];
    const int tid = threadIdx.x;
    const int tx = tid & 31, ty = tid >> 5;   // tx: 2 nodes, ty: 4 cols
    const int nodeBase = blockIdx.x*64;

    unsigned long long acc[2][2];
    acc[0][0]=acc[0][1]=acc[1][0]=acc[1][1]=0ull;

    const float* srcs[6] = { g_C, g_U1, g_U2, g_C, g_U1 + (size_t)NODES*FP, g_U2 + (size_t)NODES*FP };

    for (int t=0;t<6;t++){
        __syncthreads();
        for (int i = tid*4; i < 66*32; i += 1024)
            *(float4*)&Ws[i] = *(const float4*)&upd_w[t*66*32 + i];
        for (int i = tid; i < 64*66; i += 256){
            int n = i/66, k = i - n*66;
            xs[n][k] = srcs[t][(size_t)(nodeBase+n)*FP + k];
        }
        __syncthreads();
        for (int k=0;k<66;k++){
            const float x0 = xs[tx*2][k], x1 = xs[tx*2+1][k];
            const unsigned long long xd0 = pk2(x0,x0), xd1 = pk2(x1,x1);
            #pragma unroll
            for (int j=0;j<2;j++){
                const unsigned long long w = *(const unsigned long long*)&Ws[k*32 + ty*4 + 2*j];
                fma2(acc[0][j], xd0, w);
                fma2(acc[1][j], xd1, w);
            }
        }
    }
    __syncthreads();
    #pragma unroll
    for (int i=0;i<2;i++){
        const int n = tx*2+i, node = nodeBase+n;
        #pragma unroll
        for (int j=0;j<2;j++){
            const float2 p = upk2(acc[i][j]);
            #pragma unroll
            for (int q=0;q<2;q++){
                const int col = ty*4 + 2*j + q;
                const float hcp = (q ? p.y : p.x) + upd_b[col];
                const float hc = tanhf(hcp);
                const float rr = g_r[node*32+col];
                const float st = g_state[node*32+col];
                const float h = rr*st + (1.f-rr)*hc;
                hbuf[n][col] = h;
                out[(size_t)node*32 + col] = h;
            }
        }
    }
    for (int i = tid; i < 1024; i += 256) hw[i] = hop_w[i];
    __syncthreads();
    for (int i = tid; i < 64*32; i += 256){
        const int n = i >> 5, o = i & 31;
        float a = hop_b[o];
        #pragma unroll
        for (int j=0;j<32;j++) a += hbuf[n][j]*hw[j*32+o];
        out[(size_t)NODES*32 + (size_t)(nodeBase+n)*32 + o] = a;
    }
}

// ---------------- launch ----------------
extern "C" void kernel_launch(void* const* d_in, const int* in_sizes, int n_in,
                              void* d_out, int out_size)
{
    (void)in_sizes; (void)n_in; (void)out_size;
    const float* xt       = (const float*)d_in[0];
    const float* s1       = (const float*)d_in[1];
    const float* s2       = (const float*)d_in[2];
    const float* ge       = (const float*)d_in[3];
    const float* supports = (const float*)d_in[4];
    const float* mlp_w    = (const float*)d_in[5];
    const float* mlp_b    = (const float*)d_in[6];
    const float* gate_w   = (const float*)d_in[7];
    const float* gate_b   = (const float*)d_in[8];
    const float* upd_w    = (const float*)d_in[9];
    const float* upd_b    = (const float*)d_in[10];
    const float* hop_w    = (const float*)d_in[11];
    const float* hop_b    = (const float*)d_in[12];
    float* out = (float*)d_out;

    float *pX, *pC, *pT1, *pT2, *pU1, *pU2;
    cudaGetSymbolAddress((void**)&pX,  g_X);
    cudaGetSymbolAddress((void**)&pC,  g_C);
    cudaGetSymbolAddress((void**)&pT1, g_T1);
    cudaGetSymbolAddress((void**)&pT2, g_T2);
    cudaGetSymbolAddress((void**)&pU1, g_U1);
    cudaGetSymbolAddress((void**)&pU2, g_U2);

    setup_kernel<<<NODES/128, 128>>>(xt, s1, s2, ge, mlp_w, mlp_b);

    dim3 gg(NN/TM, BB, 2);
    big_gemm<<<gg, 288>>>(supports, pX,  pT1, nullptr, 0, 0);   // T1 = A @ X
    big_gemm<<<gg, 288>>>(supports, pT1, pT2, pX,      1, 1);   // T2 = 2A@T1 - X
    gate_kernel<<<NODES/64, 256>>>(gate_w, gate_b, xt, s1, s2);
    big_gemm<<<gg, 288>>>(supports, pC,  pU1, nullptr, 0, 0);   // U1 = A @ C
    big_gemm<<<gg, 288>>>(supports, pU1, pU2, pC,      1, 1);   // U2 = 2A@U1 - C
    final_kernel<<<NODES/64, 256>>>(upd_w, upd_b, hop_w, hop_b, out);
}

// round 5
// speedup vs baseline: 1.5674x; 1.5674x over previous
#include <cuda_runtime.h>
#include <cuda_bf16.h>
#include <cstddef>

#define BB 8
#define NN 2048
#define NODES (BB*NN)          // 16384
#define FP 72                  // padded feature width (66 real)
#define DSZ 32
#define BM 128
#define BK 32

// ---------------- scratch (device globals, no allocation) ----------------
__device__ float g_X[NODES*FP];
__device__ float g_C[NODES*FP];
__device__ float g_state[NODES*DSZ];
__device__ float g_r[NODES*DSZ];
__device__ float g_T1[2*NODES*FP];
__device__ float g_T2[2*NODES*FP];
__device__ float g_U1[2*NODES*FP];
__device__ float g_U2[2*NODES*FP];

// ---------------- helpers ----------------
__device__ __forceinline__ unsigned long long pk2(float lo, float hi){
    unsigned long long r;
    asm("mov.b64 %0, {%1,%2};" : "=l"(r) : "f"(lo), "f"(hi));
    return r;
}
__device__ __forceinline__ void fma2(unsigned long long &d, unsigned long long a, unsigned long long b){
    asm("fma.rn.f32x2 %0, %1, %2, %0;" : "+l"(d) : "l"(a), "l"(b));
}
__device__ __forceinline__ float2 upk2(unsigned long long v){
    float lo, hi;
    asm("mov.b64 {%0,%1}, %2;" : "=f"(lo), "=f"(hi) : "l"(v));
    return make_float2(lo, hi);
}
__device__ __forceinline__ float sigmoidf_(float x){ return 1.f/(1.f+__expf(-x)); }

__device__ __forceinline__ void mma_bf16(float acc[4],
    unsigned a0, unsigned a1, unsigned a2, unsigned a3, unsigned b0, unsigned b1)
{
    asm volatile("mma.sync.aligned.m16n8k16.row.col.f32.bf16.bf16.f32 "
        "{%0,%1,%2,%3},{%4,%5,%6,%7},{%8,%9},{%0,%1,%2,%3};"
        : "+f"(acc[0]), "+f"(acc[1]), "+f"(acc[2]), "+f"(acc[3])
        : "r"(a0), "r"(a1), "r"(a2), "r"(a3), "r"(b0), "r"(b1));
}

__device__ __forceinline__ void cvsplit(float v, __nv_bfloat16 &h, __nv_bfloat16 &l){
    h = __float2bfloat16(v);
    l = __float2bfloat16(v - __bfloat162float(h));
}

// ---------------- setup: mr/state + padded X ----------------
__global__ void setup_kernel(const float* __restrict__ xt, const float* __restrict__ s1,
                             const float* __restrict__ s2, const float* __restrict__ ge,
                             const float* __restrict__ mlp_w, const float* __restrict__ mlp_b)
{
    __shared__ float w[74*32];
    __shared__ float wb[32];
    const int tid = threadIdx.x;
    for (int i = tid; i < 74*32; i += blockDim.x) w[i] = mlp_w[i];
    if (tid < 32) wb[tid] = mlp_b[tid];
    __syncthreads();

    const int node = blockIdx.x*blockDim.x + tid;

    float in[74];
    #pragma unroll
    for (int i=0;i<2;i++)  in[i]    = xt[node*2+i];
    #pragma unroll
    for (int i=0;i<32;i++) in[2+i]  = s1[node*32+i];
    #pragma unroll
    for (int i=0;i<32;i++) in[34+i] = s2[node*32+i];
    #pragma unroll
    for (int i=0;i<8;i++)  in[66+i] = ge[node*8+i];

    float acc[32];
    #pragma unroll
    for (int o=0;o<32;o++) acc[o] = wb[o];
    for (int i=0;i<74;i++){
        float v = in[i];
        #pragma unroll
        for (int o=0;o<32;o++) acc[o] += v * w[i*32+o];
    }
    #pragma unroll
    for (int o=0;o<32;o++){
        float mr = sigmoidf_(acc[o]);
        g_state[node*32+o] = mr*in[2+o] + (1.f-mr)*in[34+o];
    }

    float* X = g_X + (size_t)node*FP;
    X[0]=in[0]; X[1]=in[1];
    #pragma unroll
    for (int i=0;i<32;i++){ X[2+i]=in[2+i]; X[34+i]=in[34+i]; }
    #pragma unroll
    for (int i=66;i<FP;i++) X[i]=0.f;
}

// ---------------- big GEMM (tensor cores, split-bf16) ----------------
// C[128 x 72] tile of A(2048x2048) @ In(2048x72). grid (16, B, 2supports), 256 thr (8 warps x m16).
// smem (dynamic, bf16 elems):
//  AsH [2][128][40] @ 0        (10240 elems)
//  AsL [2][128][40] @ 10240
//  XsH [2][72][40]  @ 20480    (5760 elems)   stored TRANSPOSED: [n][k]
//  XsL [2][72][40]  @ 26240
// total 32000 elems = 64000 bytes
__global__ __launch_bounds__(256, 2)
void mma_gemm(const float* __restrict__ Abase, const float* __restrict__ Inbase,
              float* __restrict__ Outbase, const float* __restrict__ Subbase,
              int inPerSupport, int combo)
{
    extern __shared__ __nv_bfloat16 sm[];
    __nv_bfloat16* AsH = sm;
    __nv_bfloat16* AsL = sm + 10240;
    __nv_bfloat16* XsH = sm + 20480;
    __nv_bfloat16* XsL = sm + 26240;

    const int b = blockIdx.y, s = blockIdx.z;
    const int sb = s*BB + b;
    const float* A  = Abase + (size_t)sb*NN*NN;
    const float* In = Inbase + (size_t)(inPerSupport ? sb : b)*NN*FP;
    float* Out = Outbase + (size_t)sb*NN*FP;

    const int tid = threadIdx.x;
    const int warp = tid >> 5, lane = tid & 31;
    const int gid = lane >> 2, tig = lane & 3;
    const int rowBase = blockIdx.x * BM;

    float acc[9][4];
    #pragma unroll
    for (int j=0;j<9;j++)
        #pragma unroll
        for (int q=0;q<4;q++) acc[j][q] = 0.f;

    float4 ast[4];
    float4 xst[3];

    // ---- prologue: tile 0 ----
    #pragma unroll
    for (int i=0;i<4;i++){
        const int f = tid + i*256, r = f>>3, c4 = f&7;
        ast[i] = *(const float4*)(A + (size_t)(rowBase + r)*NN + c4*4);
    }
    #pragma unroll
    for (int i=0;i<3;i++){
        const int f = tid + i*256;
        if (f < 576){
            const int r = f/18, c4 = f%18;
            xst[i] = *(const float4*)(In + (size_t)r*FP + c4*4);
        }
    }
    // store tile 0 -> buffer 0
    #pragma unroll
    for (int i=0;i<4;i++){
        const int f = tid + i*256, r = f>>3, c4 = f&7;
        __nv_bfloat16 h0,l0,h1,l1,h2,l2,h3,l3;
        cvsplit(ast[i].x,h0,l0); cvsplit(ast[i].y,h1,l1);
        cvsplit(ast[i].z,h2,l2); cvsplit(ast[i].w,h3,l3);
        const int off = r*40 + c4*4;
        *(__nv_bfloat162*)&AsH[off]   = __halves2bfloat162(h0,h1);
        *(__nv_bfloat162*)&AsH[off+2] = __halves2bfloat162(h2,h3);
        *(__nv_bfloat162*)&AsL[off]   = __halves2bfloat162(l0,l1);
        *(__nv_bfloat162*)&AsL[off+2] = __halves2bfloat162(l2,l3);
    }
    #pragma unroll
    for (int i=0;i<3;i++){
        const int f = tid + i*256;
        if (f < 576){
            const int r = f/18, c4 = f%18;
            float v[4] = {xst[i].x, xst[i].y, xst[i].z, xst[i].w};
            #pragma unroll
            for (int e=0;e<4;e++){
                __nv_bfloat16 h,l; cvsplit(v[e],h,l);
                const int n = c4*4+e;
                XsH[n*40 + r] = h;
                XsL[n*40 + r] = l;
            }
        }
    }
    __syncthreads();

    int cur = 0;
    for (int t = 0; t < NN/BK; t++){
        const int k0n = (t+1)*BK;
        if (t+1 < NN/BK){
            #pragma unroll
            for (int i=0;i<4;i++){
                const int f = tid + i*256, r = f>>3, c4 = f&7;
                ast[i] = *(const float4*)(A + (size_t)(rowBase + r)*NN + k0n + c4*4);
            }
            #pragma unroll
            for (int i=0;i<3;i++){
                const int f = tid + i*256;
                if (f < 576){
                    const int r = f/18, c4 = f%18;
                    xst[i] = *(const float4*)(In + (size_t)(k0n + r)*FP + c4*4);
                }
            }
        }

        // ---- compute on buffer cur (2 k16 steps) ----
        #pragma unroll
        for (int s16=0; s16<2; s16++){
            const int abase = cur*5120 + (warp*16+gid)*40 + s16*16 + tig*2;
            const unsigned aH0 = *(const unsigned*)&AsH[abase];
            const unsigned aH1 = *(const unsigned*)&AsH[abase + 8*40];
            const unsigned aH2 = *(const unsigned*)&AsH[abase + 8];
            const unsigned aH3 = *(const unsigned*)&AsH[abase + 8*40 + 8];
            const unsigned aL0 = *(const unsigned*)&AsL[abase];
            const unsigned aL1 = *(const unsigned*)&AsL[abase + 8*40];
            const unsigned aL2 = *(const unsigned*)&AsL[abase + 8];
            const unsigned aL3 = *(const unsigned*)&AsL[abase + 8*40 + 8];
            #pragma unroll
            for (int j=0;j<9;j++){
                const int bbase = cur*2880 + (j*8+gid)*40 + s16*16 + tig*2;
                const unsigned bH0 = *(const unsigned*)&XsH[bbase];
                const unsigned bH1 = *(const unsigned*)&XsH[bbase + 8];
                const unsigned bL0 = *(const unsigned*)&XsL[bbase];
                const unsigned bL1 = *(const unsigned*)&XsL[bbase + 8];
                mma_bf16(acc[j], aH0,aH1,aH2,aH3, bH0,bH1);
                mma_bf16(acc[j], aH0,aH1,aH2,aH3, bL0,bL1);
                mma_bf16(acc[j], aL0,aL1,aL2,aL3, bH0,bH1);
            }
        }

        if (t+1 < NN/BK){
            const int nxt = cur ^ 1;
            #pragma unroll
            for (int i=0;i<4;i++){
                const int f = tid + i*256, r = f>>3, c4 = f&7;
                __nv_bfloat16 h0,l0,h1,l1,h2,l2,h3,l3;
                cvsplit(ast[i].x,h0,l0); cvsplit(ast[i].y,h1,l1);
                cvsplit(ast[i].z,h2,l2); cvsplit(ast[i].w,h3,l3);
                const int off = nxt*5120 + r*40 + c4*4;
                *(__nv_bfloat162*)&AsH[off]   = __halves2bfloat162(h0,h1);
                *(__nv_bfloat162*)&AsH[off+2] = __halves2bfloat162(h2,h3);
                *(__nv_bfloat162*)&AsL[off]   = __halves2bfloat162(l0,l1);
                *(__nv_bfloat162*)&AsL[off+2] = __halves2bfloat162(l2,l3);
            }
            #pragma unroll
            for (int i=0;i<3;i++){
                const int f = tid + i*256;
                if (f < 576){
                    const int r = f/18, c4 = f%18;
                    float v[4] = {xst[i].x, xst[i].y, xst[i].z, xst[i].w};
                    #pragma unroll
                    for (int e=0;e<4;e++){
                        __nv_bfloat16 h,l; cvsplit(v[e],h,l);
                        const int n = c4*4+e;
                        XsH[nxt*2880 + n*40 + r] = h;
                        XsL[nxt*2880 + n*40 + r] = l;
                    }
                }
            }
        }
        __syncthreads();
        cur ^= 1;
    }

    // ---- epilogue ----
    const float* Sub = Subbase + (size_t)b*NN*FP;
    #pragma unroll
    for (int j=0;j<9;j++){
        const int row = rowBase + warp*16 + gid;
        const int col = j*8 + tig*2;
        float2 v0 = make_float2(acc[j][0], acc[j][1]);
        float2 v1 = make_float2(acc[j][2], acc[j][3]);
        if (combo){
            const float2 s0 = *(const float2*)(Sub + (size_t)row*FP + col);
            const float2 s1v = *(const float2*)(Sub + (size_t)(row+8)*FP + col);
            v0.x = 2.f*v0.x - s0.x;  v0.y = 2.f*v0.y - s0.y;
            v1.x = 2.f*v1.x - s1v.x; v1.y = 2.f*v1.y - s1v.y;
        }
        *(float2*)(Out + (size_t)row*FP + col)     = v0;
        *(float2*)(Out + (size_t)(row+8)*FP + col) = v1;
    }
}

// ---------------- gate: zz = sigmoid(xg @ gate_w + b); build C, r ----------------
// 32 nodes/block, 256 threads: tx=node (32), ty=col-group (8 x 12 cols = 96)
__global__ __launch_bounds__(256)
void gate_kernel(const float* __restrict__ gate_w, const float* __restrict__ gate_b,
                 const float* __restrict__ xt, const float* __restrict__ s1, const float* __restrict__ s2)
{
    __shared__ __align__(16) float Ws[6336];   // 66*96, reused as zbuf[32*96] after
    __shared__ float xs[32][67];
    const int tid = threadIdx.x;
    const int tx = tid & 31, ty = tid >> 5;
    const int nodeBase = blockIdx.x*32;

    unsigned long long acc[6];
    #pragma unroll
    for (int j=0;j<6;j++) acc[j]=0ull;

    const float* srcs[6] = { g_X, g_T1, g_T2, g_X, g_T1 + (size_t)NODES*FP, g_T2 + (size_t)NODES*FP };

    for (int t=0;t<6;t++){
        __syncthreads();
        for (int i = tid*4; i < 6336; i += 1024)
            *(float4*)&Ws[i] = *(const float4*)&gate_w[t*6336 + i];
        for (int i = tid; i < 32*66; i += 256){
            const int n = i/66, k = i - n*66;
            xs[n][k] = srcs[t][(size_t)(nodeBase+n)*FP + k];
        }
        __syncthreads();
        for (int k=0;k<66;k++){
            const float x0 = xs[tx][k];
            const unsigned long long xd = pk2(x0,x0);
            #pragma unroll
            for (int j=0;j<6;j++){
                const unsigned long long w = *(const unsigned long long*)&Ws[k*96 + ty*12 + 2*j];
                fma2(acc[j], xd, w);
            }
        }
    }
    __syncthreads();
    float* zbuf = Ws;
    #pragma unroll
    for (int j=0;j<6;j++){
        const float2 p = upk2(acc[j]);
        const int col = ty*12 + 2*j;
        zbuf[tx*96 + col]   = sigmoidf_(p.x + gate_b[col]);
        zbuf[tx*96 + col+1] = sigmoidf_(p.y + gate_b[col+1]);
    }
    __syncthreads();
    for (int i = tid; i < 32*32; i += 256){
        const int n = i >> 5, o = i & 31;
        const int node = nodeBase + n;
        const float z1 = zbuf[n*96+o], z2 = zbuf[n*96+32+o], rr = zbuf[n*96+64+o];
        g_C[(size_t)node*FP + 2 + o]  = z1 * s1[node*32+o];
        g_C[(size_t)node*FP + 34 + o] = z2 * s2[node*32+o];
        g_r[node*32+o] = rr;
    }
    if (tid < 32){
        const int node = nodeBase + tid;
        g_C[(size_t)node*FP + 0] = xt[node*2+0];
        g_C[(size_t)node*FP + 1] = xt[node*2+1];
        #pragma unroll
        for (int p=66;p<FP;p++) g_C[(size_t)node*FP + p] = 0.f;
    }
}

// ---------------- final: hc = tanh(xg' @ upd_w + b); h; trans ----------------
// 32 nodes/block, 256 threads: tx=node (32), ty=col-group (8 x 4 cols = 32)
__global__ __launch_bounds__(256)
void final_kernel(const float* __restrict__ upd_w, const float* __restrict__ upd_b,
                  const float* __restrict__ hop_w, const float* __restrict__ hop_b,
                  float* __restrict__ out)
{
    __shared__ __align__(16) float Ws[2112];   // 66*32
    __shared__ float xs[32][67];
    __shared__ float hbuf[32][33];
    __shared__ float hw[1024];
    const int tid = threadIdx.x;
    const int tx = tid & 31, ty = tid >> 5;
    const int nodeBase = blockIdx.x*32;

    unsigned long long acc[2];
    acc[0]=acc[1]=0ull;

    const float* srcs[6] = { g_C, g_U1, g_U2, g_C, g_U1 + (size_t)NODES*FP, g_U2 + (size_t)NODES*FP };

    for (int t=0;t<6;t++){
        __syncthreads();
        for (int i = tid*4; i < 2112; i += 1024)
            *(float4*)&Ws[i] = *(const float4*)&upd_w[t*2112 + i];
        for (int i = tid; i < 32*66; i += 256){
            const int n = i/66, k = i - n*66;
            xs[n][k] = srcs[t][(size_t)(nodeBase+n)*FP + k];
        }
        __syncthreads();
        for (int k=0;k<66;k++){
            const float x0 = xs[tx][k];
            const unsigned long long xd = pk2(x0,x0);
            #pragma unroll
            for (int j=0;j<2;j++){
                const unsigned long long w = *(const unsigned long long*)&Ws[k*32 + ty*4 + 2*j];
                fma2(acc[j], xd, w);
            }
        }
    }

    const int node = nodeBase + tx;
    #pragma unroll
    for (int j=0;j<2;j++){
        const float2 p = upk2(acc[j]);
        #pragma unroll
        for (int q=0;q<2;q++){
            const int col = ty*4 + 2*j + q;
            const float hc = tanhf((q ? p.y : p.x) + upd_b[col]);
            const float rr = g_r[node*32+col];
            const float st = g_state[node*32+col];
            const float h = rr*st + (1.f-rr)*hc;
            hbuf[tx][col] = h;
            out[(size_t)node*32 + col] = h;
        }
    }
    for (int i = tid; i < 1024; i += 256) hw[i] = hop_w[i];
    __syncthreads();
    for (int i = tid; i < 1024; i += 256){
        const int n = i >> 5, o = i & 31;
        float a = hop_b[o];
        #pragma unroll
        for (int j=0;j<32;j++) a += hbuf[n][j]*hw[j*32+o];
        out[(size_t)NODES*32 + (size_t)(nodeBase+n)*32 + o] = a;
    }
}

// ---------------- launch ----------------
extern "C" void kernel_launch(void* const* d_in, const int* in_sizes, int n_in,
                              void* d_out, int out_size)
{
    (void)in_sizes; (void)n_in; (void)out_size;
    const float* xt       = (const float*)d_in[0];
    const float* s1       = (const float*)d_in[1];
    const float* s2       = (const float*)d_in[2];
    const float* ge       = (const float*)d_in[3];
    const float* supports = (const float*)d_in[4];
    const float* mlp_w    = (const float*)d_in[5];
    const float* mlp_b    = (const float*)d_in[6];
    const float* gate_w   = (const float*)d_in[7];
    const float* gate_b   = (const float*)d_in[8];
    const float* upd_w    = (const float*)d_in[9];
    const float* upd_b    = (const float*)d_in[10];
    const float* hop_w    = (const float*)d_in[11];
    const float* hop_b    = (const float*)d_in[12];
    float* out = (float*)d_out;

    float *pX, *pC, *pT1, *pT2, *pU1, *pU2;
    cudaGetSymbolAddress((void**)&pX,  g_X);
    cudaGetSymbolAddress((void**)&pC,  g_C);
    cudaGetSymbolAddress((void**)&pT1, g_T1);
    cudaGetSymbolAddress((void**)&pT2, g_T2);
    cudaGetSymbolAddress((void**)&pU1, g_U1);
    cudaGetSymbolAddress((void**)&pU2, g_U2);

    const int SMEM_BYTES = 64000;
    cudaFuncSetAttribute(mma_gemm, cudaFuncAttributeMaxDynamicSharedMemorySize, SMEM_BYTES);

    setup_kernel<<<NODES/128, 128>>>(xt, s1, s2, ge, mlp_w, mlp_b);

    dim3 gg(NN/BM, BB, 2);
    mma_gemm<<<gg, 256, SMEM_BYTES>>>(supports, pX,  pT1, pX, 0, 0);   // T1 = A @ X
    mma_gemm<<<gg, 256, SMEM_BYTES>>>(supports, pT1, pT2, pX, 1, 1);   // T2 = 2A@T1 - X
    gate_kernel<<<NODES/32, 256>>>(gate_w, gate_b, xt, s1, s2);
    mma_gemm<<<gg, 256, SMEM_BYTES>>>(supports, pC,  pU1, pC, 0, 0);   // U1 = A @ C
    mma_gemm<<<gg, 256, SMEM_BYTES>>>(supports, pU1, pU2, pC, 1, 1);   // U2 = 2A@U1 - C
    final_kernel<<<NODES/32, 256>>>(upd_w, upd_b, hop_w, hop_b, out);
}

// round 6
// speedup vs baseline: 1.8634x; 1.1888x over previous
#include <cuda_runtime.h>
#include <cuda_bf16.h>
#include <cstddef>

#define BB 8
#define NN 2048
#define NODES (BB*NN)          // 16384
#define FP 72                  // padded feature width (66 real)
#define DSZ 32
#define BM 128
#define BK 32
#define NT (NN/BK)             // 64 k-tiles
#define STAGE_E 16000          // bf16 elems per pipeline stage
#define NSTAGE 3

// ---------------- scratch (device globals, no allocation) ----------------
__device__ float g_X[NODES*FP];
__device__ float g_C[NODES*FP];
__device__ float g_state[NODES*DSZ];
__device__ float g_r[NODES*DSZ];
__device__ float g_T1[2*NODES*FP];
__device__ float g_T2[2*NODES*FP];
__device__ float g_U1[2*NODES*FP];
__device__ float g_U2[2*NODES*FP];

// pre-split A planes (bf16 hi/lo), 134MB each
__device__ __align__(16) __nv_bfloat16 g_Ah[16ull*NN*NN];
__device__ __align__(16) __nv_bfloat16 g_Al[16ull*NN*NN];
// transposed/split dense-input planes [plane][72][2048]
__device__ __align__(16) __nv_bfloat16 g_InTh[16ull*FP*NN];
__device__ __align__(16) __nv_bfloat16 g_InTl[16ull*FP*NN];

// ---------------- helpers ----------------
__device__ __forceinline__ unsigned long long pk2(float lo, float hi){
    unsigned long long r;
    asm("mov.b64 %0, {%1,%2};" : "=l"(r) : "f"(lo), "f"(hi));
    return r;
}
__device__ __forceinline__ void fma2(unsigned long long &d, unsigned long long a, unsigned long long b){
    asm("fma.rn.f32x2 %0, %1, %2, %0;" : "+l"(d) : "l"(a), "l"(b));
}
__device__ __forceinline__ float2 upk2(unsigned long long v){
    float lo, hi;
    asm("mov.b64 {%0,%1}, %2;" : "=f"(lo), "=f"(hi) : "l"(v));
    return make_float2(lo, hi);
}
__device__ __forceinline__ float sigmoidf_(float x){ return 1.f/(1.f+__expf(-x)); }

__device__ __forceinline__ void mma_bf16(float acc[4],
    unsigned a0, unsigned a1, unsigned a2, unsigned a3, unsigned b0, unsigned b1)
{
    asm volatile("mma.sync.aligned.m16n8k16.row.col.f32.bf16.bf16.f32 "
        "{%0,%1,%2,%3},{%4,%5,%6,%7},{%8,%9},{%0,%1,%2,%3};"
        : "+f"(acc[0]), "+f"(acc[1]), "+f"(acc[2]), "+f"(acc[3])
        : "r"(a0), "r"(a1), "r"(a2), "r"(a3), "r"(b0), "r"(b1));
}
__device__ __forceinline__ void ldsm4(unsigned r[4], unsigned addr){
    asm volatile("ldmatrix.sync.aligned.m8n8.x4.shared.b16 {%0,%1,%2,%3}, [%4];"
        : "=r"(r[0]), "=r"(r[1]), "=r"(r[2]), "=r"(r[3]) : "r"(addr));
}
__device__ __forceinline__ void cvsplit(float v, __nv_bfloat16 &h, __nv_bfloat16 &l){
    h = __float2bfloat16(v);
    l = __float2bfloat16(v - __bfloat162float(h));
}
__device__ __forceinline__ unsigned smem_u32(const void* p){
    unsigned a;
    asm("{ .reg .u64 t; cvta.to.shared.u64 t, %1; cvt.u32.u64 %0, t; }" : "=r"(a) : "l"(p));
    return a;
}

// ---------------- split A: fp32 -> bf16 hi/lo planes ----------------
__global__ void splitA_kernel(const float* __restrict__ A)
{
    const size_t idx = (size_t)blockIdx.x*256 + threadIdx.x;   // float4 index
    const float4 v = ((const float4*)A)[idx];
    __nv_bfloat16 h0,l0,h1,l1,h2,l2,h3,l3;
    cvsplit(v.x,h0,l0); cvsplit(v.y,h1,l1); cvsplit(v.z,h2,l2); cvsplit(v.w,h3,l3);
    ((__nv_bfloat162*)g_Ah)[2*idx]   = __halves2bfloat162(h0,h1);
    ((__nv_bfloat162*)g_Ah)[2*idx+1] = __halves2bfloat162(h2,h3);
    ((__nv_bfloat162*)g_Al)[2*idx]   = __halves2bfloat162(l0,l1);
    ((__nv_bfloat162*)g_Al)[2*idx+1] = __halves2bfloat162(l2,l3);
}

// ---------------- transpose+split dense input: [P][2048][72] fp32 -> [P][72][2048] bf16 h/l ----
__global__ __launch_bounds__(256)
void splitT_kernel(const float* __restrict__ in)
{
    __shared__ float xs[64][73];
    const int tid = threadIdx.x;
    const int p = blockIdx.y;
    const int nodeBase = blockIdx.x*64;
    const float* src = in + ((size_t)p*NN + nodeBase)*FP;
    for (int i = tid; i < 64*FP; i += 256){
        const int n = i/FP, k = i - n*FP;
        xs[n][k] = src[(size_t)n*FP + k];
    }
    __syncthreads();
    __nv_bfloat16* oh = g_InTh + (size_t)p*FP*NN + nodeBase;
    __nv_bfloat16* ol = g_InTl + (size_t)p*FP*NN + nodeBase;
    for (int i = tid; i < FP*64; i += 256){
        const int k = i >> 6, n = i & 63;
        __nv_bfloat16 h,l; cvsplit(xs[n][k], h, l);
        oh[(size_t)k*NN + n] = h;
        ol[(size_t)k*NN + n] = l;
    }
}

// ---------------- setup: mr/state + padded X ----------------
__global__ void setup_kernel(const float* __restrict__ xt, const float* __restrict__ s1,
                             const float* __restrict__ s2, const float* __restrict__ ge,
                             const float* __restrict__ mlp_w, const float* __restrict__ mlp_b)
{
    __shared__ float w[74*32];
    __shared__ float wb[32];
    const int tid = threadIdx.x;
    for (int i = tid; i < 74*32; i += blockDim.x) w[i] = mlp_w[i];
    if (tid < 32) wb[tid] = mlp_b[tid];
    __syncthreads();

    const int node = blockIdx.x*blockDim.x + tid;

    float in[74];
    #pragma unroll
    for (int i=0;i<2;i++)  in[i]    = xt[node*2+i];
    #pragma unroll
    for (int i=0;i<32;i++) in[2+i]  = s1[node*32+i];
    #pragma unroll
    for (int i=0;i<32;i++) in[34+i] = s2[node*32+i];
    #pragma unroll
    for (int i=0;i<8;i++)  in[66+i] = ge[node*8+i];

    float acc[32];
    #pragma unroll
    for (int o=0;o<32;o++) acc[o] = wb[o];
    for (int i=0;i<74;i++){
        float v = in[i];
        #pragma unroll
        for (int o=0;o<32;o++) acc[o] += v * w[i*32+o];
    }
    #pragma unroll
    for (int o=0;o<32;o++){
        float mr = sigmoidf_(acc[o]);
        g_state[node*32+o] = mr*in[2+o] + (1.f-mr)*in[34+o];
    }

    float* X = g_X + (size_t)node*FP;
    X[0]=in[0]; X[1]=in[1];
    #pragma unroll
    for (int i=0;i<32;i++){ X[2+i]=in[2+i]; X[34+i]=in[34+i]; }
    #pragma unroll
    for (int i=66;i<FP;i++) X[i]=0.f;
}

// ---------------- big GEMM v2: cp.async pipeline + ldmatrix + split-bf16 HMMA ----------------
// smem per stage (bf16 elems): Ah[128][40]@0, Al@5120, Xh[72][40]@10240, Xl@13120  -> 16000
__global__ __launch_bounds__(256, 2)
void mma_gemm2(float* __restrict__ Outbase, const float* __restrict__ Subbase,
               int inPerSupport, int combo)
{
    extern __shared__ __align__(16) __nv_bfloat16 sm2[];
    const unsigned smBase = smem_u32(sm2);

    const int b = blockIdx.y, s = blockIdx.z;
    const int sb = s*BB + b;
    const int ip = inPerSupport ? sb : b;
    const __nv_bfloat16* Ah_g = g_Ah + (size_t)sb*NN*NN;
    const __nv_bfloat16* Al_g = g_Al + (size_t)sb*NN*NN;
    const __nv_bfloat16* Xh_g = g_InTh + (size_t)ip*FP*NN;
    const __nv_bfloat16* Xl_g = g_InTl + (size_t)ip*FP*NN;
    float* Out = Outbase + (size_t)sb*NN*FP;

    const int tid = threadIdx.x;
    const int warp = tid >> 5, lane = tid & 31;
    const int gid = lane >> 2, tig = lane & 3;
    const int rowBase = blockIdx.x * BM;

    // ---- precompute cp.async chunk map (1600 16B-chunks per stage) ----
    const __nv_bfloat16* pSrc[7];
    unsigned dOff[7];
    int nCh = 0;
    #pragma unroll
    for (int ii = 0; ii < 7; ii++){
        const int i = tid + ii*256;
        if (i < 1600){
            int c = i;
            const __nv_bfloat16* base; unsigned d;
            if (c < 512){ base = Ah_g; d = 0; }
            else if (c < 1024){ c -= 512; base = Al_g; d = 5120; }
            else if (c < 1312){ c -= 1024; base = Xh_g; d = 10240; }
            else { c -= 1312; base = Xl_g; d = 13120; }
            const int row = c >> 2, quad = c & 3;
            const size_t grow = (d < 10240) ? (size_t)(rowBase + row) : (size_t)row;
            pSrc[nCh] = base + grow*NN + quad*8;
            dOff[nCh] = d + row*40 + quad*8;
            nCh++;
        }
    }

    #define ISSUE_STAGE(SOFF, K0) do { \
        _Pragma("unroll") \
        for (int c = 0; c < 7; c++) if (c < nCh){ \
            const unsigned dst = smBase + ((SOFF) + dOff[c])*2; \
            const __nv_bfloat16* sp = pSrc[c] + (K0); \
            asm volatile("cp.async.cg.shared.global [%0], [%1], 16;" :: "r"(dst), "l"(sp)); \
        } \
        asm volatile("cp.async.commit_group;"); \
    } while(0)

    float acc[9][4];
    #pragma unroll
    for (int j=0;j<9;j++)
        #pragma unroll
        for (int q=0;q<4;q++) acc[j][q] = 0.f;

    // lane-static fragment addresses (elem offsets within stage)
    const unsigned aStat = (unsigned)((warp*16 + ((lane>>3)&1)*8 + (lane&7))*40 + ((lane>>4)&1)*8);
    const unsigned bStat = (unsigned)((lane&7)*40 + (lane>>3)*8);

    // prologue: stages 0,1
    ISSUE_STAGE(0, 0);
    ISSUE_STAGE(STAGE_E, BK);

    for (int t = 0; t < NT; t++){
        const unsigned sOff = (unsigned)((t % NSTAGE) * STAGE_E);
        if (t < NT-1) asm volatile("cp.async.wait_group 1;");
        else          asm volatile("cp.async.wait_group 0;");
        __syncthreads();

        unsigned aH[2][4], aL[2][4];
        #pragma unroll
        for (int s16=0;s16<2;s16++){
            ldsm4(aH[s16], smBase + (sOff + aStat + s16*16)*2);
            ldsm4(aL[s16], smBase + (sOff + 5120 + aStat + s16*16)*2);
        }
        #pragma unroll
        for (int j=0;j<9;j++){
            unsigned bh[4], bl[4];
            ldsm4(bh, smBase + (sOff + 10240 + j*320 + bStat)*2);
            ldsm4(bl, smBase + (sOff + 13120 + j*320 + bStat)*2);
            mma_bf16(acc[j], aH[0][0],aH[0][1],aH[0][2],aH[0][3], bh[0],bh[1]);
            mma_bf16(acc[j], aH[0][0],aH[0][1],aH[0][2],aH[0][3], bl[0],bl[1]);
            mma_bf16(acc[j], aL[0][0],aL[0][1],aL[0][2],aL[0][3], bh[0],bh[1]);
            mma_bf16(acc[j], aH[1][0],aH[1][1],aH[1][2],aH[1][3], bh[2],bh[3]);
            mma_bf16(acc[j], aH[1][0],aH[1][1],aH[1][2],aH[1][3], bl[2],bl[3]);
            mma_bf16(acc[j], aL[1][0],aL[1][1],aL[1][2],aL[1][3], bh[2],bh[3]);
        }

        if (t + 2 < NT){
            ISSUE_STAGE(((t+2) % NSTAGE) * STAGE_E, (t+2)*BK);
        }
    }
    #undef ISSUE_STAGE

    // ---- epilogue ----
    const float* Sub = Subbase + (size_t)b*NN*FP;
    #pragma unroll
    for (int j=0;j<9;j++){
        const int row = rowBase + warp*16 + gid;
        const int col = j*8 + tig*2;
        float2 v0 = make_float2(acc[j][0], acc[j][1]);
        float2 v1 = make_float2(acc[j][2], acc[j][3]);
        if (combo){
            const float2 s0  = *(const float2*)(Sub + (size_t)row*FP + col);
            const float2 s1v = *(const float2*)(Sub + (size_t)(row+8)*FP + col);
            v0.x = 2.f*v0.x - s0.x;  v0.y = 2.f*v0.y - s0.y;
            v1.x = 2.f*v1.x - s1v.x; v1.y = 2.f*v1.y - s1v.y;
        }
        *(float2*)(Out + (size_t)row*FP + col)     = v0;
        *(float2*)(Out + (size_t)(row+8)*FP + col) = v1;
    }
}

// ---------------- gate: zz = sigmoid(xg @ gate_w + b); build C, r ----------------
// 64 nodes/block, 256 threads: lane tx -> 2 nodes, warp ty -> 12 cols (8x12=96)
__global__ __launch_bounds__(256)
void gate_kernel(const float* __restrict__ gate_w, const float* __restrict__ gate_b,
                 const float* __restrict__ xt, const float* __restrict__ s1, const float* __restrict__ s2)
{
    __shared__ __align__(16) float Ws[6336];   // 66*96, reused as zbuf[64*96]
    __shared__ float xs[66][66];               // [k][node], 64 nodes + pad
    const int tid = threadIdx.x;
    const int tx = tid & 31, ty = tid >> 5;
    const int nodeBase = blockIdx.x*64;

    unsigned long long acc[2][6];
    #pragma unroll
    for (int i=0;i<2;i++)
        #pragma unroll
        for (int j=0;j<6;j++) acc[i][j]=0ull;

    const float* srcs[6] = { g_X, g_T1, g_T2, g_X, g_T1 + (size_t)NODES*FP, g_T2 + (size_t)NODES*FP };

    for (int t=0;t<6;t++){
        __syncthreads();
        for (int i = tid*4; i < 6336; i += 1024)
            *(float4*)&Ws[i] = *(const float4*)&gate_w[t*6336 + i];
        for (int i = tid; i < 64*66; i += 256){
            const int n = i/66, k = i - n*66;
            xs[k][n] = srcs[t][(size_t)(nodeBase+n)*FP + k];
        }
        __syncthreads();
        for (int k=0;k<66;k++){
            const float4 w0 = *(const float4*)&Ws[k*96 + ty*12];
            const float4 w1 = *(const float4*)&Ws[k*96 + ty*12 + 4];
            const float4 w2 = *(const float4*)&Ws[k*96 + ty*12 + 8];
            const float2 xv = *(const float2*)&xs[k][tx*2];
            const unsigned long long xd0 = pk2(xv.x,xv.x), xd1 = pk2(xv.y,xv.y);
            const unsigned long long wp[6] = { pk2(w0.x,w0.y), pk2(w0.z,w0.w),
                                               pk2(w1.x,w1.y), pk2(w1.z,w1.w),
                                               pk2(w2.x,w2.y), pk2(w2.z,w2.w) };
            #pragma unroll
            for (int j=0;j<6;j++){
                fma2(acc[0][j], xd0, wp[j]);
                fma2(acc[1][j], xd1, wp[j]);
            }
        }
    }
    __syncthreads();
    float* zbuf = Ws;
    #pragma unroll
    for (int i=0;i<2;i++){
        const int n = tx*2 + i;
        #pragma unroll
        for (int j=0;j<6;j++){
            const float2 p = upk2(acc[i][j]);
            const int col = ty*12 + 2*j;
            zbuf[n*96 + col]   = sigmoidf_(p.x + gate_b[col]);
            zbuf[n*96 + col+1] = sigmoidf_(p.y + gate_b[col+1]);
        }
    }
    __syncthreads();
    for (int i = tid; i < 64*32; i += 256){
        const int n = i >> 5, o = i & 31;
        const int node = nodeBase + n;
        const float z1 = zbuf[n*96+o], z2 = zbuf[n*96+32+o], rr = zbuf[n*96+64+o];
        g_C[(size_t)node*FP + 2 + o]  = z1 * s1[node*32+o];
        g_C[(size_t)node*FP + 34 + o] = z2 * s2[node*32+o];
        g_r[node*32+o] = rr;
    }
    if (tid < 64){
        const int node = nodeBase + tid;
        g_C[(size_t)node*FP + 0] = xt[node*2+0];
        g_C[(size_t)node*FP + 1] = xt[node*2+1];
        #pragma unroll
        for (int p=66;p<FP;p++) g_C[(size_t)node*FP + p] = 0.f;
    }
}

// ---------------- final: hc = tanh(xg' @ upd_w + b); h; trans ----------------
// 64 nodes/block, 256 threads: lane tx -> 2 nodes, warp ty -> 4 cols
__global__ __launch_bounds__(256)
void final_kernel(const float* __restrict__ upd_w, const float* __restrict__ upd_b,
                  const float* __restrict__ hop_w, const float* __restrict__ hop_b,
                  float* __restrict__ out)
{
    __shared__ __align__(16) float Ws[2112];   // 66*32
    __shared__ float xs[66][66];
    __shared__ float hbuf[64][33];
    __shared__ float hw[1024];
    const int tid = threadIdx.x;
    const int tx = tid & 31, ty = tid >> 5;
    const int nodeBase = blockIdx.x*64;

    unsigned long long acc[2][2];
    acc[0][0]=acc[0][1]=acc[1][0]=acc[1][1]=0ull;

    const float* srcs[6] = { g_C, g_U1, g_U2, g_C, g_U1 + (size_t)NODES*FP, g_U2 + (size_t)NODES*FP };

    for (int t=0;t<6;t++){
        __syncthreads();
        for (int i = tid*4; i < 2112; i += 1024)
            *(float4*)&Ws[i] = *(const float4*)&upd_w[t*2112 + i];
        for (int i = tid; i < 64*66; i += 256){
            const int n = i/66, k = i - n*66;
            xs[k][n] = srcs[t][(size_t)(nodeBase+n)*FP + k];
        }
        __syncthreads();
        for (int k=0;k<66;k++){
            const float4 w = *(const float4*)&Ws[k*32 + ty*4];
            const float2 xv = *(const float2*)&xs[k][tx*2];
            const unsigned long long xd0 = pk2(xv.x,xv.x), xd1 = pk2(xv.y,xv.y);
            const unsigned long long w0 = pk2(w.x,w.y), w1 = pk2(w.z,w.w);
            fma2(acc[0][0], xd0, w0); fma2(acc[0][1], xd0, w1);
            fma2(acc[1][0], xd1, w0); fma2(acc[1][1], xd1, w1);
        }
    }

    #pragma unroll
    for (int i=0;i<2;i++){
        const int n = tx*2 + i, node = nodeBase + n;
        #pragma unroll
        for (int j=0;j<2;j++){
            const float2 p = upk2(acc[i][j]);
            #pragma unroll
            for (int q=0;q<2;q++){
                const int col = ty*4 + 2*j + q;
                const float hc = tanhf((q ? p.y : p.x) + upd_b[col]);
                const float rr = g_r[node*32+col];
                const float st = g_state[node*32+col];
                const float h = rr*st + (1.f-rr)*hc;
                hbuf[n][col] = h;
                out[(size_t)node*32 + col] = h;
            }
        }
    }
    for (int i = tid; i < 1024; i += 256) hw[i] = hop_w[i];
    __syncthreads();
    for (int i = tid; i < 64*32; i += 256){
        const int n = i >> 5, o = i & 31;
        float a = hop_b[o];
        #pragma unroll
        for (int j=0;j<32;j++) a += hbuf[n][j]*hw[j*32+o];
        out[(size_t)NODES*32 + (size_t)(nodeBase+n)*32 + o] = a;
    }
}

// ---------------- launch ----------------
extern "C" void kernel_launch(void* const* d_in, const int* in_sizes, int n_in,
                              void* d_out, int out_size)
{
    (void)in_sizes; (void)n_in; (void)out_size;
    const float* xt       = (const float*)d_in[0];
    const float* s1       = (const float*)d_in[1];
    const float* s2       = (const float*)d_in[2];
    const float* ge       = (const float*)d_in[3];
    const float* supports = (const float*)d_in[4];
    const float* mlp_w    = (const float*)d_in[5];
    const float* mlp_b    = (const float*)d_in[6];
    const float* gate_w   = (const float*)d_in[7];
    const float* gate_b   = (const float*)d_in[8];
    const float* upd_w    = (const float*)d_in[9];
    const float* upd_b    = (const float*)d_in[10];
    const float* hop_w    = (const float*)d_in[11];
    const float* hop_b    = (const float*)d_in[12];
    float* out = (float*)d_out;

    float *pX, *pC, *pT1, *pT2, *pU1, *pU2;
    cudaGetSymbolAddress((void**)&pX,  g_X);
    cudaGetSymbolAddress((void**)&pC,  g_C);
    cudaGetSymbolAddress((void**)&pT1, g_T1);
    cudaGetSymbolAddress((void**)&pT2, g_T2);
    cudaGetSymbolAddress((void**)&pU1, g_U1);
    cudaGetSymbolAddress((void**)&pU2, g_U2);

    const int SMEM_BYTES = NSTAGE * STAGE_E * 2;   // 96000
    cudaFuncSetAttribute(mma_gemm2, cudaFuncAttributeMaxDynamicSharedMemorySize, SMEM_BYTES);

    setup_kernel<<<NODES/128, 128>>>(xt, s1, s2, ge, mlp_w, mlp_b);
    splitA_kernel<<<(16u*NN*NN)/4/256, 256>>>(supports);
    splitT_kernel<<<dim3(NN/64, BB), 256>>>(pX);

    dim3 gg(NN/BM, BB, 2);
    mma_gemm2<<<gg, 256, SMEM_BYTES>>>(pT1, pX, 0, 0);   // T1 = A @ X
    splitT_kernel<<<dim3(NN/64, 16), 256>>>(pT1);
    mma_gemm2<<<gg, 256, SMEM_BYTES>>>(pT2, pX, 1, 1);   // T2 = 2A@T1 - X
    gate_kernel<<<NODES/64, 256>>>(gate_w, gate_b, xt, s1, s2);
    splitT_kernel<<<dim3(NN/64, BB), 256>>>(pC);
    mma_gemm2<<<gg, 256, SMEM_BYTES>>>(pU1, pC, 0, 0);   // U1 = A @ C
    splitT_kernel<<<dim3(NN/64, 16), 256>>>(pU1);
    mma_gemm2<<<gg, 256, SMEM_BYTES>>>(pU2, pC, 1, 1);   // U2 = 2A@U1 - C
    final_kernel<<<NODES/64, 256>>>(upd_w, upd_b, hop_w, hop_b, out);
}

// round 7
// speedup vs baseline: 2.1421x; 1.1496x over previous
#include <cuda_runtime.h>
#include <cuda_bf16.h>
#include <cstddef>

#define BB 8
#define NN 2048
#define NODES (BB*NN)          // 16384
#define FP 72                  // padded feature width (66 real)
#define DSZ 32
#define BM 128
#define BK 32
#define NT (NN/BK)             // 64 k-tiles
#define STAGE_E 16000          // bf16 elems per pipeline stage
#define NSTAGE 3

// ---------------- scratch (device globals, no allocation) ----------------
__device__ float g_X[NODES*FP];
__device__ float g_C[NODES*FP];
__device__ float g_state[NODES*DSZ];
__device__ float g_r[NODES*DSZ];
__device__ float g_T1[2*NODES*FP];
__device__ float g_T2[2*NODES*FP];
__device__ float g_U1[2*NODES*FP];
__device__ float g_U2[2*NODES*FP];

// pre-split A planes (bf16 hi/lo)
__device__ __align__(16) __nv_bfloat16 g_Ah[16ull*NN*NN];
__device__ __align__(16) __nv_bfloat16 g_Al[16ull*NN*NN];
// transposed/split dense-input planes [plane][72][2048]
__device__ __align__(16) __nv_bfloat16 g_InTh[16ull*FP*NN];
__device__ __align__(16) __nv_bfloat16 g_InTl[16ull*FP*NN];

// ---------------- helpers ----------------
__device__ __forceinline__ unsigned long long pk2(float lo, float hi){
    unsigned long long r;
    asm("mov.b64 %0, {%1,%2};" : "=l"(r) : "f"(lo), "f"(hi));
    return r;
}
__device__ __forceinline__ void fma2(unsigned long long &d, unsigned long long a, unsigned long long b){
    asm("fma.rn.f32x2 %0, %1, %2, %0;" : "+l"(d) : "l"(a), "l"(b));
}
__device__ __forceinline__ float2 upk2(unsigned long long v){
    float lo, hi;
    asm("mov.b64 {%0,%1}, %2;" : "=f"(lo), "=f"(hi) : "l"(v));
    return make_float2(lo, hi);
}
__device__ __forceinline__ float sigmoidf_(float x){ return 1.f/(1.f+__expf(-x)); }

__device__ __forceinline__ void mma_bf16(float acc[4],
    unsigned a0, unsigned a1, unsigned a2, unsigned a3, unsigned b0, unsigned b1)
{
    asm volatile("mma.sync.aligned.m16n8k16.row.col.f32.bf16.bf16.f32 "
        "{%0,%1,%2,%3},{%4,%5,%6,%7},{%8,%9},{%0,%1,%2,%3};"
        : "+f"(acc[0]), "+f"(acc[1]), "+f"(acc[2]), "+f"(acc[3])
        : "r"(a0), "r"(a1), "r"(a2), "r"(a3), "r"(b0), "r"(b1));
}
__device__ __forceinline__ void ldsm4(unsigned r[4], unsigned addr){
    asm volatile("ldmatrix.sync.aligned.m8n8.x4.shared.b16 {%0,%1,%2,%3}, [%4];"
        : "=r"(r[0]), "=r"(r[1]), "=r"(r[2]), "=r"(r[3]) : "r"(addr));
}
__device__ __forceinline__ void cvsplit(float v, __nv_bfloat16 &h, __nv_bfloat16 &l){
    h = __float2bfloat16(v);
    l = __float2bfloat16(v - __bfloat162float(h));
}
__device__ __forceinline__ unsigned smem_u32(const void* p){
    unsigned a;
    asm("{ .reg .u64 t; cvta.to.shared.u64 t, %1; cvt.u32.u64 %0, t; }" : "=r"(a) : "l"(p));
    return a;
}

// ---------------- split A: fp32 -> bf16 hi/lo planes (8 floats/thread) ----------------
__global__ void splitA_kernel(const float* __restrict__ A)
{
    const size_t idx = ((size_t)blockIdx.x*256 + threadIdx.x)*2;   // float4 pair index
    const float4 v0 = ((const float4*)A)[idx];
    const float4 v1 = ((const float4*)A)[idx+1];
    uint4 ho, lo;
    __nv_bfloat162* hp = (__nv_bfloat162*)&ho;
    __nv_bfloat162* lp = (__nv_bfloat162*)&lo;
    __nv_bfloat16 h[8], l[8];
    cvsplit(v0.x,h[0],l[0]); cvsplit(v0.y,h[1],l[1]); cvsplit(v0.z,h[2],l[2]); cvsplit(v0.w,h[3],l[3]);
    cvsplit(v1.x,h[4],l[4]); cvsplit(v1.y,h[5],l[5]); cvsplit(v1.z,h[6],l[6]); cvsplit(v1.w,h[7],l[7]);
    #pragma unroll
    for (int i=0;i<4;i++){ hp[i] = __halves2bfloat162(h[2*i],h[2*i+1]); lp[i] = __halves2bfloat162(l[2*i],l[2*i+1]); }
    ((uint4*)g_Ah)[idx/2] = ho;
    ((uint4*)g_Al)[idx/2] = lo;
}

// ---------------- transpose+split dense input ----------------
__global__ __launch_bounds__(256)
void splitT_kernel(const float* __restrict__ in)
{
    __shared__ float xs[64][73];
    const int tid = threadIdx.x;
    const int p = blockIdx.y;
    const int nodeBase = blockIdx.x*64;
    const float* src = in + ((size_t)p*NN + nodeBase)*FP;
    for (int i = tid; i < 64*18; i += 256){
        const int n = i/18, q = i - n*18;
        const float4 v = *(const float4*)&src[(size_t)n*FP + q*4];
        xs[n][q*4+0]=v.x; xs[n][q*4+1]=v.y; xs[n][q*4+2]=v.z; xs[n][q*4+3]=v.w;
    }
    __syncthreads();
    __nv_bfloat16* oh = g_InTh + (size_t)p*FP*NN + nodeBase;
    __nv_bfloat16* ol = g_InTl + (size_t)p*FP*NN + nodeBase;
    for (int i = tid; i < FP*64; i += 256){
        const int k = i >> 6, n = i & 63;
        __nv_bfloat16 h,l; cvsplit(xs[n][k], h, l);
        oh[(size_t)k*NN + n] = h;
        ol[(size_t)k*NN + n] = l;
    }
}

// ---------------- setup: mr/state + padded X ----------------
__global__ void setup_kernel(const float* __restrict__ xt, const float* __restrict__ s1,
                             const float* __restrict__ s2, const float* __restrict__ ge,
                             const float* __restrict__ mlp_w, const float* __restrict__ mlp_b)
{
    __shared__ float w[74*32];
    __shared__ float wb[32];
    const int tid = threadIdx.x;
    for (int i = tid; i < 74*32; i += blockDim.x) w[i] = mlp_w[i];
    if (tid < 32) wb[tid] = mlp_b[tid];
    __syncthreads();

    const int node = blockIdx.x*blockDim.x + tid;

    float in[74];
    #pragma unroll
    for (int i=0;i<2;i++)  in[i]    = xt[node*2+i];
    #pragma unroll
    for (int i=0;i<32;i++) in[2+i]  = s1[node*32+i];
    #pragma unroll
    for (int i=0;i<32;i++) in[34+i] = s2[node*32+i];
    #pragma unroll
    for (int i=0;i<8;i++)  in[66+i] = ge[node*8+i];

    float acc[32];
    #pragma unroll
    for (int o=0;o<32;o++) acc[o] = wb[o];
    for (int i=0;i<74;i++){
        float v = in[i];
        #pragma unroll
        for (int o=0;o<32;o++) acc[o] += v * w[i*32+o];
    }
    #pragma unroll
    for (int o=0;o<32;o++){
        float mr = sigmoidf_(acc[o]);
        g_state[node*32+o] = mr*in[2+o] + (1.f-mr)*in[34+o];
    }

    float* X = g_X + (size_t)node*FP;
    X[0]=in[0]; X[1]=in[1];
    #pragma unroll
    for (int i=0;i<32;i++){ X[2+i]=in[2+i]; X[34+i]=in[34+i]; }
    #pragma unroll
    for (int i=66;i<FP;i++) X[i]=0.f;
}

// ---------------- big GEMM v3: pipelined fragments ----------------
// stage (bf16 elems): Ah[128][40]@0, Al@5120, Xh[72][40]@10240, Xl@13120 -> 16000
__global__ __launch_bounds__(256, 2)
void mma_gemm3(float* __restrict__ Outbase, const float* __restrict__ Subbase,
               int inPerSupport, int combo)
{
    extern __shared__ __align__(16) __nv_bfloat16 sm2[];
    const unsigned smBase = smem_u32(sm2);

    const int b = blockIdx.y, s = blockIdx.z;
    const int sb = s*BB + b;
    const int ip = inPerSupport ? sb : b;
    const __nv_bfloat16* Ah_g = g_Ah + (size_t)sb*NN*NN;
    const __nv_bfloat16* Al_g = g_Al + (size_t)sb*NN*NN;
    const __nv_bfloat16* Xh_g = g_InTh + (size_t)ip*FP*NN;
    const __nv_bfloat16* Xl_g = g_InTl + (size_t)ip*FP*NN;
    float* Out = Outbase + (size_t)sb*NN*FP;

    const int tid = threadIdx.x;
    const int warp = tid >> 5, lane = tid & 31;
    const int gid = lane >> 2, tig = lane & 3;
    const int rowBase = blockIdx.x * BM;

    // ---- cp.async chunk map (1600 16B-chunks per stage) ----
    const __nv_bfloat16* pSrc[7];
    unsigned dOff[7];
    int nCh = 0;
    #pragma unroll
    for (int ii = 0; ii < 7; ii++){
        const int i = tid + ii*256;
        if (i < 1600){
            int c = i;
            const __nv_bfloat16* base; unsigned d;
            if (c < 512){ base = Ah_g; d = 0; }
            else if (c < 1024){ c -= 512; base = Al_g; d = 5120; }
            else if (c < 1312){ c -= 1024; base = Xh_g; d = 10240; }
            else { c -= 1312; base = Xl_g; d = 13120; }
            const int row = c >> 2, quad = c & 3;
            const size_t grow = (d < 10240) ? (size_t)(rowBase + row) : (size_t)row;
            pSrc[nCh] = base + grow*NN + quad*8;
            dOff[nCh] = d + row*40 + quad*8;
            nCh++;
        }
    }

    #define ISSUE_STAGE(SOFF, K0) do { \
        _Pragma("unroll") \
        for (int c = 0; c < 7; c++) if (c < nCh){ \
            const unsigned dst = smBase + ((SOFF) + dOff[c])*2; \
            const __nv_bfloat16* sp = pSrc[c] + (K0); \
            asm volatile("cp.async.cg.shared.global [%0], [%1], 16;" :: "r"(dst), "l"(sp)); \
        } \
        asm volatile("cp.async.commit_group;"); \
    } while(0)

    float acc[9][4];
    #pragma unroll
    for (int j=0;j<9;j++)
        #pragma unroll
        for (int q=0;q<4;q++) acc[j][q] = 0.f;

    const unsigned aStat = (unsigned)((warp*16 + ((lane>>3)&1)*8 + (lane&7))*40 + ((lane>>4)&1)*8);
    const unsigned bStat = (unsigned)((lane&7)*40 + (lane>>3)*8);

    unsigned AH0[2][4], AL0[2][4], AH1[2][4], AL1[2][4];
    unsigned BH[2][4], BL[2][4];

    #define LDSM_A(SOFF, AH, AL) do { \
        ldsm4(AH[0], smBase + ((SOFF) + aStat)*2); \
        ldsm4(AH[1], smBase + ((SOFF) + aStat + 16)*2); \
        ldsm4(AL[0], smBase + ((SOFF) + 5120 + aStat)*2); \
        ldsm4(AL[1], smBase + ((SOFF) + 5120 + aStat + 16)*2); \
    } while(0)
    #define LDSM_B(SOFF, J, BHD, BLD) do { \
        ldsm4(BHD, smBase + ((SOFF) + 10240 + (J)*320 + bStat)*2); \
        ldsm4(BLD, smBase + ((SOFF) + 13120 + (J)*320 + bStat)*2); \
    } while(0)

    // prologue: stages 0,1
    ISSUE_STAGE(0, 0);
    ISSUE_STAGE(STAGE_E, BK);
    asm volatile("cp.async.wait_group 0;");
    __syncthreads();
    LDSM_A(0u, AH0, AL0);
    LDSM_B(0u, 0, BH[0], BL[0]);

    #define STEP(T, AHC, ALC, AHN, ALN, P0) do { \
        const int t_ = (T); \
        const unsigned sOff  = (unsigned)((t_ % 3) * STAGE_E); \
        const unsigned sOffN = (unsigned)(((t_+1) % 3) * STAGE_E); \
        asm volatile("cp.async.wait_group 0;"); \
        __syncthreads(); \
        if (t_ + 2 < NT) ISSUE_STAGE(((t_+2)%3)*STAGE_E, (t_+2)*BK); \
        if (t_ + 1 < NT) LDSM_A(sOffN, AHN, ALN); \
        _Pragma("unroll") \
        for (int j=0;j<9;j++){ \
            const int pc = (j + (P0)) & 1, pn = pc ^ 1; \
            if (j < 8) LDSM_B(sOff, j+1, BH[pn], BL[pn]); \
            else if (t_ + 1 < NT) LDSM_B(sOffN, 0, BH[pn], BL[pn]); \
            mma_bf16(acc[j], AHC[0][0],AHC[0][1],AHC[0][2],AHC[0][3], BH[pc][0],BH[pc][1]); \
            mma_bf16(acc[j], AHC[0][0],AHC[0][1],AHC[0][2],AHC[0][3], BL[pc][0],BL[pc][1]); \
            mma_bf16(acc[j], ALC[0][0],ALC[0][1],ALC[0][2],ALC[0][3], BH[pc][0],BH[pc][1]); \
            mma_bf16(acc[j], AHC[1][0],AHC[1][1],AHC[1][2],AHC[1][3], BH[pc][2],BH[pc][3]); \
            mma_bf16(acc[j], AHC[1][0],AHC[1][1],AHC[1][2],AHC[1][3], BL[pc][2],BL[pc][3]); \
            mma_bf16(acc[j], ALC[1][0],ALC[1][1],ALC[1][2],ALC[1][3], BH[pc][2],BH[pc][3]); \
        } \
    } while(0)

    for (int t = 0; t < NT; t += 2){
        STEP(t,   AH0, AL0, AH1, AL1, 0);
        STEP(t+1, AH1, AL1, AH0, AL0, 1);
    }
    #undef STEP
    #undef LDSM_A
    #undef LDSM_B
    #undef ISSUE_STAGE

    // ---- epilogue ----
    const float* Sub = Subbase + (size_t)b*NN*FP;
    #pragma unroll
    for (int j=0;j<9;j++){
        const int row = rowBase + warp*16 + gid;
        const int col = j*8 + tig*2;
        float2 v0 = make_float2(acc[j][0], acc[j][1]);
        float2 v1 = make_float2(acc[j][2], acc[j][3]);
        if (combo){
            const float2 s0  = *(const float2*)(Sub + (size_t)row*FP + col);
            const float2 s1v = *(const float2*)(Sub + (size_t)(row+8)*FP + col);
            v0.x = 2.f*v0.x - s0.x;  v0.y = 2.f*v0.y - s0.y;
            v1.x = 2.f*v1.x - s1v.x; v1.y = 2.f*v1.y - s1v.y;
        }
        *(float2*)(Out + (size_t)row*FP + col)     = v0;
        *(float2*)(Out + (size_t)(row+8)*FP + col) = v1;
    }
}

// ---------------- gate ----------------
__global__ __launch_bounds__(256)
void gate_kernel(const float* __restrict__ gate_w, const float* __restrict__ gate_b,
                 const float* __restrict__ xt, const float* __restrict__ s1, const float* __restrict__ s2)
{
    __shared__ __align__(16) float Ws[6336];   // 66*96, reused as zbuf[64*96]
    __shared__ float xs[72][66];               // [k][node]
    const int tid = threadIdx.x;
    const int tx = tid & 31, ty = tid >> 5;
    const int nodeBase = blockIdx.x*64;

    unsigned long long acc[2][6];
    #pragma unroll
    for (int i=0;i<2;i++)
        #pragma unroll
        for (int j=0;j<6;j++) acc[i][j]=0ull;

    const float* srcs[6] = { g_X, g_T1, g_T2, g_X, g_T1 + (size_t)NODES*FP, g_T2 + (size_t)NODES*FP };

    for (int t=0;t<6;t++){
        __syncthreads();
        for (int i = tid*4; i < 6336; i += 1024)
            *(float4*)&Ws[i] = *(const float4*)&gate_w[t*6336 + i];
        const float* src = srcs[t] + (size_t)nodeBase*FP;
        for (int i = tid; i < 64*18; i += 256){
            const int n = i/18, q = i - n*18;
            const float4 v = *(const float4*)&src[(size_t)n*FP + q*4];
            xs[q*4+0][n]=v.x; xs[q*4+1][n]=v.y; xs[q*4+2][n]=v.z; xs[q*4+3][n]=v.w;
        }
        __syncthreads();
        for (int k=0;k<66;k++){
            const float4 w0 = *(const float4*)&Ws[k*96 + ty*12];
            const float4 w1 = *(const float4*)&Ws[k*96 + ty*12 + 4];
            const float4 w2 = *(const float4*)&Ws[k*96 + ty*12 + 8];
            const float2 xv = *(const float2*)&xs[k][tx*2];
            const unsigned long long xd0 = pk2(xv.x,xv.x), xd1 = pk2(xv.y,xv.y);
            const unsigned long long wp[6] = { pk2(w0.x,w0.y), pk2(w0.z,w0.w),
                                               pk2(w1.x,w1.y), pk2(w1.z,w1.w),
                                               pk2(w2.x,w2.y), pk2(w2.z,w2.w) };
            #pragma unroll
            for (int j=0;j<6;j++){
                fma2(acc[0][j], xd0, wp[j]);
                fma2(acc[1][j], xd1, wp[j]);
            }
        }
    }
    __syncthreads();
    float* zbuf = Ws;
    #pragma unroll
    for (int i=0;i<2;i++){
        const int n = tx*2 + i;
        #pragma unroll
        for (int j=0;j<6;j++){
            const float2 p = upk2(acc[i][j]);
            const int col = ty*12 + 2*j;
            zbuf[n*96 + col]   = sigmoidf_(p.x + gate_b[col]);
            zbuf[n*96 + col+1] = sigmoidf_(p.y + gate_b[col+1]);
        }
    }
    __syncthreads();
    for (int i = tid; i < 64*32; i += 256){
        const int n = i >> 5, o = i & 31;
        const int node = nodeBase + n;
        const float z1 = zbuf[n*96+o], z2 = zbuf[n*96+32+o], rr = zbuf[n*96+64+o];
        g_C[(size_t)node*FP + 2 + o]  = z1 * s1[node*32+o];
        g_C[(size_t)node*FP + 34 + o] = z2 * s2[node*32+o];
        g_r[node*32+o] = rr;
    }
    if (tid < 64){
        const int node = nodeBase + tid;
        g_C[(size_t)node*FP + 0] = xt[node*2+0];
        g_C[(size_t)node*FP + 1] = xt[node*2+1];
        #pragma unroll
        for (int p=66;p<FP;p++) g_C[(size_t)node*FP + p] = 0.f;
    }
}

// ---------------- final ----------------
__global__ __launch_bounds__(256)
void final_kernel(const float* __restrict__ upd_w, const float* __restrict__ upd_b,
                  const float* __restrict__ hop_w, const float* __restrict__ hop_b,
                  float* __restrict__ out)
{
    __shared__ __align__(16) float Ws[2112];   // 66*32
    __shared__ float xs[72][66];
    __shared__ float hbuf[64][33];
    __shared__ float hw[1024];
    const int tid = threadIdx.x;
    const int tx = tid & 31, ty = tid >> 5;
    const int nodeBase = blockIdx.x*64;

    unsigned long long acc[2][2];
    acc[0][0]=acc[0][1]=acc[1][0]=acc[1][1]=0ull;

    const float* srcs[6] = { g_C, g_U1, g_U2, g_C, g_U1 + (size_t)NODES*FP, g_U2 + (size_t)NODES*FP };

    for (int t=0;t<6;t++){
        __syncthreads();
        for (int i = tid*4; i < 2112; i += 1024)
            *(float4*)&Ws[i] = *(const float4*)&upd_w[t*2112 + i];
        const float* src = srcs[t] + (size_t)nodeBase*FP;
        for (int i = tid; i < 64*18; i += 256){
            const int n = i/18, q = i - n*18;
            const float4 v = *(const float4*)&src[(size_t)n*FP + q*4];
            xs[q*4+0][n]=v.x; xs[q*4+1][n]=v.y; xs[q*4+2][n]=v.z; xs[q*4+3][n]=v.w;
        }
        __syncthreads();
        for (int k=0;k<66;k++){
            const float4 w = *(const float4*)&Ws[k*32 + ty*4];
            const float2 xv = *(const float2*)&xs[k][tx*2];
            const unsigned long long xd0 = pk2(xv.x,xv.x), xd1 = pk2(xv.y,xv.y);
            const unsigned long long w0 = pk2(w.x,w.y), w1 = pk2(w.z,w.w);
            fma2(acc[0][0], xd0, w0); fma2(acc[0][1], xd0, w1);
            fma2(acc[1][0], xd1, w0); fma2(acc[1][1], xd1, w1);
        }
    }

    #pragma unroll
    for (int i=0;i<2;i++){
        const int n = tx*2 + i, node = nodeBase + n;
        #pragma unroll
        for (int j=0;j<2;j++){
            const float2 p = upk2(acc[i][j]);
            #pragma unroll
            for (int q=0;q<2;q++){
                const int col = ty*4 + 2*j + q;
                const float hc = tanhf((q ? p.y : p.x) + upd_b[col]);
                const float rr = g_r[node*32+col];
                const float st = g_state[node*32+col];
                const float h = rr*st + (1.f-rr)*hc;
                hbuf[n][col] = h;
                out[(size_t)node*32 + col] = h;
            }
        }
    }
    for (int i = tid; i < 1024; i += 256) hw[i] = hop_w[i];
    __syncthreads();
    for (int i = tid; i < 64*32; i += 256){
        const int n = i >> 5, o = i & 31;
        float a = hop_b[o];
        #pragma unroll
        for (int j=0;j<32;j++) a += hbuf[n][j]*hw[j*32+o];
        out[(size_t)NODES*32 + (size_t)(nodeBase+n)*32 + o] = a;
    }
}

// ---------------- launch ----------------
extern "C" void kernel_launch(void* const* d_in, const int* in_sizes, int n_in,
                              void* d_out, int out_size)
{
    (void)in_sizes; (void)n_in; (void)out_size;
    const float* xt       = (const float*)d_in[0];
    const float* s1       = (const float*)d_in[1];
    const float* s2       = (const float*)d_in[2];
    const float* ge       = (const float*)d_in[3];
    const float* supports = (const float*)d_in[4];
    const float* mlp_w    = (const float*)d_in[5];
    const float* mlp_b    = (const float*)d_in[6];
    const float* gate_w   = (const float*)d_in[7];
    const float* gate_b   = (const float*)d_in[8];
    const float* upd_w    = (const float*)d_in[9];
    const float* upd_b    = (const float*)d_in[10];
    const float* hop_w    = (const float*)d_in[11];
    const float* hop_b    = (const float*)d_in[12];
    float* out = (float*)d_out;

    float *pX, *pC, *pT1, *pT2, *pU1, *pU2;
    cudaGetSymbolAddress((void**)&pX,  g_X);
    cudaGetSymbolAddress((void**)&pC,  g_C);
    cudaGetSymbolAddress((void**)&pT1, g_T1);
    cudaGetSymbolAddress((void**)&pT2, g_T2);
    cudaGetSymbolAddress((void**)&pU1, g_U1);
    cudaGetSymbolAddress((void**)&pU2, g_U2);

    const int SMEM_BYTES = NSTAGE * STAGE_E * 2;   // 96000
    cudaFuncSetAttribute(mma_gemm3, cudaFuncAttributeMaxDynamicSharedMemorySize, SMEM_BYTES);

    setup_kernel<<<NODES/128, 128>>>(xt, s1, s2, ge, mlp_w, mlp_b);
    splitA_kernel<<<(16u*NN*NN)/8/256, 256>>>(supports);
    splitT_kernel<<<dim3(NN/64, BB), 256>>>(pX);

    dim3 gg(NN/BM, BB, 2);
    mma_gemm3<<<gg, 256, SMEM_BYTES>>>(pT1, pX, 0, 0);   // T1 = A @ X
    splitT_kernel<<<dim3(NN/64, 16), 256>>>(pT1);
    mma_gemm3<<<gg, 256, SMEM_BYTES>>>(pT2, pX, 1, 1);   // T2 = 2A@T1 - X
    gate_kernel<<<NODES/64, 256>>>(gate_w, gate_b, xt, s1, s2);
    splitT_kernel<<<dim3(NN/64, BB), 256>>>(pC);
    mma_gemm3<<<gg, 256, SMEM_BYTES>>>(pU1, pC, 0, 0);   // U1 = A @ C
    splitT_kernel<<<dim3(NN/64, 16), 256>>>(pU1);
    mma_gemm3<<<gg, 256, SMEM_BYTES>>>(pU2, pC, 1, 1);   // U2 = 2A@U1 - C
    final_kernel<<<NODES/64, 256>>>(upd_w, upd_b, hop_w, hop_b, out);
}